// round 4
// baseline (speedup 1.0000x reference)
#include <cuda_runtime.h>

#define CDIM     64
#define KSLOTS   27
#define TILE     64
#define CTHREADS 128
#define NMAX     65536
#define EPAD     (KSLOTS * TILE)
#define EMAX     (1572864 + EPAD)
#define MAXSEG   1024

// ---------------- device scratch (static: no runtime allocation) ------------
__device__ float  g_bufA[(size_t)NMAX * CDIM];   // conv accumulators
__device__ float  g_bufB[(size_t)NMAX * CDIM];   // post-LN1 activations
__device__ int    g_si[EMAX];                    // sorted edge targets (pad = -1)
__device__ int    g_sj[EMAX];                    // sorted edge sources (pad = 0)
__device__ int    g_hist[KSLOTS];
__device__ int    g_aoff[KSLOTS + 1];            // tile-aligned segment offsets
__device__ int    g_cursor[KSLOTS];
__device__ int    g_segoff[MAXSEG + 1];          // ragged-sample point offsets
__device__ double g_s1[MAXSEG], g_s2[MAXSEG];
__device__ float  g_mean[MAXSEG], g_invs[MAXSEG];

// ---------------- sort prep -------------------------------------------------
__global__ void k_zero_meta() {
    int t = threadIdx.x;
    if (t < KSLOTS) g_hist[t] = 0;
}

__global__ void k_hist(const int* __restrict__ k, int E) {
    __shared__ int h[KSLOTS];
    if (threadIdx.x < KSLOTS) h[threadIdx.x] = 0;
    __syncthreads();
    for (int e = blockIdx.x * blockDim.x + threadIdx.x; e < E;
         e += gridDim.x * blockDim.x)
        atomicAdd(&h[k[e]], 1);
    __syncthreads();
    if (threadIdx.x < KSLOTS) atomicAdd(&g_hist[threadIdx.x], h[threadIdx.x]);
}

__global__ void k_scan(const int* __restrict__ ss, int B, int N) {
    if (threadIdx.x == 0 && blockIdx.x == 0) {
        int off = 0;
        for (int q = 0; q < KSLOTS; q++) {
            g_aoff[q]   = off;
            g_cursor[q] = off;
            off += ((g_hist[q] + TILE - 1) / TILE) * TILE;  // tile-align each bin
        }
        g_aoff[KSLOTS] = off;
        int p = 0;
        for (int b = 0; b < B; b++) { g_segoff[b] = p; p += ss[b]; }
        g_segoff[B] = N;
    }
}

__global__ void k_fill(int total) {
    for (int e = blockIdx.x * blockDim.x + threadIdx.x; e < total;
         e += gridDim.x * blockDim.x) {
        g_si[e] = -1;
        g_sj[e] = 0;
    }
}

__global__ void k_scatter(const int* __restrict__ i, const int* __restrict__ j,
                          const int* __restrict__ k, int E) {
    for (int e = blockIdx.x * blockDim.x + threadIdx.x; e < E;
         e += gridDim.x * blockDim.x) {
        int kk  = k[e];
        int pos = atomicAdd(&g_cursor[kk], 1);
        g_si[pos] = i[e];
        g_sj[pos] = j[e];
    }
}

// ---------------- utility ---------------------------------------------------
__global__ void k_zerobuf(float4* __restrict__ p, int n4) {
    float4 z = make_float4(0.f, 0.f, 0.f, 0.f);
    for (int q = blockIdx.x * blockDim.x + threadIdx.x; q < n4;
         q += gridDim.x * blockDim.x)
        p[q] = z;
}

// ---------------- fused gather-GEMM-scatter conv -----------------------------
// Tile = 64 edges (all of one kernel slot k), 128 threads.
// Warp w: h = w&1 selects output half [h*32, h*32+32); e = ((w>>1)<<5)|lane.
// All lanes of a warp share h -> W smem loads are pure broadcast.
__global__ void __launch_bounds__(CTHREADS)
k_conv(const float* __restrict__ xin, const float* __restrict__ Wall,
       float* __restrict__ out) {
    __shared__ float Ws[CDIM * CDIM];   // W[k], row-major [c][o]
    __shared__ float Xs[TILE * 65];     // gathered x rows, stride 65 (pad)
    __shared__ int   s_k;

    int tb = blockIdx.x * TILE;
    if (tb >= g_aoff[KSLOTS]) return;

    if (threadIdx.x == 0) {
        int kk = 0;
        while (g_aoff[kk + 1] <= tb) kk++;
        s_k = kk;
    }
    __syncthreads();
    int kk = s_k;

    // stage W[k] into smem (coalesced float4)
    const float4* Wk4 = reinterpret_cast<const float4*>(Wall + (size_t)kk * CDIM * CDIM);
    #pragma unroll
    for (int t = threadIdx.x; t < (CDIM * CDIM) / 4; t += CTHREADS)
        reinterpret_cast<float4*>(Ws)[t] = __ldg(Wk4 + t);

    int lane = threadIdx.x & 31;
    int w    = threadIdx.x >> 5;
    int h    = w & 1;
    int e    = ((w >> 1) << 5) | lane;   // 0..63

    // gather this edge's source row half into smem
    int jj = g_sj[tb + e];
    const float4* xr = reinterpret_cast<const float4*>(xin + (size_t)jj * CDIM + h * 32);
    float* xd = Xs + e * 65 + h * 32;
    #pragma unroll
    for (int q = 0; q < 8; q++) {
        float4 v = __ldg(xr + q);
        xd[4 * q + 0] = v.x; xd[4 * q + 1] = v.y;
        xd[4 * q + 2] = v.z; xd[4 * q + 3] = v.w;
    }
    __syncthreads();

    // 32 outputs per thread, packed as 16 f32x2 accumulators
    unsigned long long acc[16];
    #pragma unroll
    for (int m = 0; m < 16; m++) acc[m] = 0ull;

    const float* xrow = Xs + e * 65;
    const float* wb   = Ws + h * 32;
    #pragma unroll 4
    for (int c = 0; c < CDIM; c++) {
        float xv = xrow[c];
        unsigned long long xp;
        asm("mov.b64 %0, {%1,%1};" : "=l"(xp) : "r"(__float_as_uint(xv)));
        const ulonglong2* wv = reinterpret_cast<const ulonglong2*>(wb + c * CDIM);
        #pragma unroll
        for (int q = 0; q < 8; q++) {
            ulonglong2 w2 = wv[q];
            asm("fma.rn.f32x2 %0, %1, %2, %0;" : "+l"(acc[2 * q])     : "l"(xp), "l"(w2.x));
            asm("fma.rn.f32x2 %0, %1, %2, %0;" : "+l"(acc[2 * q + 1]) : "l"(xp), "l"(w2.y));
        }
    }

    int ii = g_si[tb + e];
    if (ii < 0) return;   // pad slot
    float* orow = out + (size_t)ii * CDIM + h * 32;
    #pragma unroll
    for (int q = 0; q < 8; q++) {
        float4 v;
        v.x = __uint_as_float((unsigned)(acc[2 * q]     & 0xffffffffull));
        v.y = __uint_as_float((unsigned)(acc[2 * q]     >> 32));
        v.z = __uint_as_float((unsigned)(acc[2 * q + 1] & 0xffffffffull));
        v.w = __uint_as_float((unsigned)(acc[2 * q + 1] >> 32));
        atomicAdd(reinterpret_cast<float4*>(orow) + q, v);   // RED.E.ADD.F32.128 (sm_90+)
    }
}

// ---------------- ragged LayerNorm ------------------------------------------
__global__ void k_zstats(int B) {
    int s = blockIdx.x * blockDim.x + threadIdx.x;
    if (s < B) { g_s1[s] = 0.0; g_s2[s] = 0.0; }
}

__global__ void k_stats(const float* __restrict__ v) {
    int seg = blockIdx.x;
    long long e0 = (long long)g_segoff[seg] * CDIM;
    long long e1 = (long long)g_segoff[seg + 1] * CDIM;
    double s1 = 0.0, s2 = 0.0;
    long long stride = (long long)gridDim.y * blockDim.x;
    for (long long idx = e0 + (long long)blockIdx.y * blockDim.x + threadIdx.x;
         idx < e1; idx += stride) {
        double d = (double)v[idx];
        s1 += d;
        s2 += d * d;
    }
    #pragma unroll
    for (int o = 16; o; o >>= 1) {
        s1 += __shfl_down_sync(0xffffffffu, s1, o);
        s2 += __shfl_down_sync(0xffffffffu, s2, o);
    }
    __shared__ double w1[8], w2[8];
    int wid = threadIdx.x >> 5, lid = threadIdx.x & 31;
    if (lid == 0) { w1[wid] = s1; w2[wid] = s2; }
    __syncthreads();
    if (threadIdx.x == 0) {
        double a = 0.0, b = 0.0;
        int nw = blockDim.x >> 5;
        for (int q = 0; q < nw; q++) { a += w1[q]; b += w2[q]; }
        atomicAdd(&g_s1[seg], a);
        atomicAdd(&g_s2[seg], b);
    }
}

__global__ void k_finalize(int B) {
    int s = blockIdx.x * blockDim.x + threadIdx.x;
    if (s < B) {
        double cnt  = (double)(g_segoff[s + 1] - g_segoff[s]) * (double)CDIM;
        double mean = g_s1[s] / cnt;
        double var  = g_s2[s] / cnt - mean * mean;
        g_mean[s] = (float)mean;
        g_invs[s] = rsqrtf((float)var + 1e-5f);
    }
}

__device__ __forceinline__ int find_seg(int p, int B) {
    int s = 0;
    #pragma unroll 1
    while (s + 1 < B && __ldg(&g_segoff[s + 1]) <= p) s++;
    return s;
}

__global__ void k_norm_relu(const float* __restrict__ v,
                            const float* __restrict__ gamma,
                            const float* __restrict__ beta,
                            float* __restrict__ o, int N, int B) {
    int total = N * (CDIM / 4);
    for (int q = blockIdx.x * blockDim.x + threadIdx.x; q < total;
         q += gridDim.x * blockDim.x) {
        int p  = q >> 4;
        int c4 = (q & 15) << 2;
        int s  = find_seg(p, B);
        float mu = g_mean[s], inv = g_invs[s];
        float4 x4 = reinterpret_cast<const float4*>(v)[q];
        float4 gg = __ldg(reinterpret_cast<const float4*>(gamma + c4));
        float4 bb = __ldg(reinterpret_cast<const float4*>(beta + c4));
        float4 r;
        r.x = fmaxf(fmaf((x4.x - mu) * inv, gg.x, bb.x), 0.f);
        r.y = fmaxf(fmaf((x4.y - mu) * inv, gg.y, bb.y), 0.f);
        r.z = fmaxf(fmaf((x4.z - mu) * inv, gg.z, bb.z), 0.f);
        r.w = fmaxf(fmaf((x4.w - mu) * inv, gg.w, bb.w), 0.f);
        reinterpret_cast<float4*>(o)[q] = r;
    }
}

__global__ void k_norm_res_relu(const float* __restrict__ v,
                                const float* __restrict__ gamma,
                                const float* __restrict__ beta,
                                const float* __restrict__ xin,
                                float* __restrict__ o, int N, int B) {
    int total = N * (CDIM / 4);
    for (int q = blockIdx.x * blockDim.x + threadIdx.x; q < total;
         q += gridDim.x * blockDim.x) {
        int p  = q >> 4;
        int c4 = (q & 15) << 2;
        int s  = find_seg(p, B);
        float mu = g_mean[s], inv = g_invs[s];
        float4 x4 = reinterpret_cast<const float4*>(v)[q];
        float4 rx = __ldg(reinterpret_cast<const float4*>(xin) + q);
        float4 gg = __ldg(reinterpret_cast<const float4*>(gamma + c4));
        float4 bb = __ldg(reinterpret_cast<const float4*>(beta + c4));
        float4 r;
        r.x = fmaxf(fmaf((x4.x - mu) * inv, gg.x, bb.x) + rx.x, 0.f);
        r.y = fmaxf(fmaf((x4.y - mu) * inv, gg.y, bb.y) + rx.y, 0.f);
        r.z = fmaxf(fmaf((x4.z - mu) * inv, gg.z, bb.z) + rx.z, 0.f);
        r.w = fmaxf(fmaf((x4.w - mu) * inv, gg.w, bb.w) + rx.w, 0.f);
        reinterpret_cast<float4*>(o)[q] = r;
    }
}

// ---------------- host-side launch sequence ---------------------------------
extern "C" void kernel_launch(void* const* d_in, const int* in_sizes, int n_in,
                              void* d_out, int out_size) {
    (void)n_in; (void)out_size;
    const float* x  = (const float*)d_in[0];
    const float* W1 = (const float*)d_in[1];
    const float* g1 = (const float*)d_in[2];
    const float* b1 = (const float*)d_in[3];
    const float* W2 = (const float*)d_in[4];
    const float* g2 = (const float*)d_in[5];
    const float* b2 = (const float*)d_in[6];
    const int*   ei = (const int*)d_in[7];
    const int*   ej = (const int*)d_in[8];
    const int*   ek = (const int*)d_in[9];
    const int*   ss = (const int*)d_in[10];

    int N = in_sizes[0] / CDIM;
    int E = in_sizes[7];
    int B = in_sizes[10];
    float* out = (float*)d_out;

    float *pA, *pB;
    cudaGetSymbolAddress((void**)&pA, g_bufA);
    cudaGetSymbolAddress((void**)&pB, g_bufB);

    // --- counting sort of edges by kernel slot (tile-aligned segments) ---
    k_zero_meta<<<1, 32>>>();
    k_hist<<<256, 256>>>(ek, E);
    k_scan<<<1, 1>>>(ss, B, N);
    int fillN = E + EPAD; if (fillN > EMAX) fillN = EMAX;
    k_fill<<<256, 256>>>(fillN);
    k_scatter<<<256, 256>>>(ei, ej, ek, E);

    int n4    = N * (CDIM / 4);
    int nb    = (E + KSLOTS * (TILE - 1) + TILE - 1) / TILE;
    int statB = (B + 255) / 256;

    // --- conv1 -> LN1 -> relu ---
    k_zerobuf<<<512, 256>>>((float4*)pA, n4);
    k_conv<<<nb, CTHREADS>>>(x, W1, pA);
    k_zstats<<<statB, 256>>>(B);
    k_stats<<<dim3(B, 128), 256>>>(pA);
    k_finalize<<<statB, 256>>>(B);
    k_norm_relu<<<512, 256>>>(pA, g1, b1, pB, N, B);

    // --- conv2 -> LN2 -> +x -> relu ---
    k_zerobuf<<<512, 256>>>((float4*)pA, n4);
    k_conv<<<nb, CTHREADS>>>(pB, W2, pA);
    k_zstats<<<statB, 256>>>(B);
    k_stats<<<dim3(B, 128), 256>>>(pA);
    k_finalize<<<statB, 256>>>(B);
    k_norm_res_relu<<<512, 256>>>(pA, g2, b2, x, out, N, B);
}

// round 5
// speedup vs baseline: 1.3560x; 1.3560x over previous
#include <cuda_runtime.h>

#define CDIM     64
#define KSLOTS   27
#define TILE     128
#define CTHREADS 128
#define NMAX     65536
#define EPAD     (KSLOTS * TILE)
#define EMAX     (1572864 + EPAD)
#define MAXSEG   1024

// ---------------- device scratch (static: no runtime allocation) ------------
__device__ float  g_bufA[(size_t)NMAX * CDIM];   // conv accumulators
__device__ float  g_bufB[(size_t)NMAX * CDIM];   // post-LN1 activations
__device__ int    g_si[EMAX];                    // sorted edge targets (pad = -1)
__device__ int    g_sj[EMAX];                    // sorted edge sources (pad = 0)
__device__ int    g_hist[KSLOTS];
__device__ int    g_aoff[KSLOTS + 1];            // tile-aligned segment offsets
__device__ int    g_cursor[KSLOTS];
__device__ int    g_segoff[MAXSEG + 1];          // ragged-sample point offsets
__device__ double g_s1[MAXSEG], g_s2[MAXSEG];
__device__ float  g_mean[MAXSEG], g_invs[MAXSEG];

// ---------------- sort prep -------------------------------------------------
__global__ void k_zero_meta() {
    int t = threadIdx.x;
    if (t < KSLOTS) g_hist[t] = 0;
}

__global__ void k_hist(const int* __restrict__ k, int E) {
    __shared__ int h[KSLOTS];
    if (threadIdx.x < KSLOTS) h[threadIdx.x] = 0;
    __syncthreads();
    for (int e = blockIdx.x * blockDim.x + threadIdx.x; e < E;
         e += gridDim.x * blockDim.x)
        atomicAdd(&h[k[e]], 1);
    __syncthreads();
    if (threadIdx.x < KSLOTS) atomicAdd(&g_hist[threadIdx.x], h[threadIdx.x]);
}

// fill pad entries AND do the (tiny) exclusive scans in one launch
__global__ void k_fill_scan(int total, const int* __restrict__ ss, int B, int N) {
    int idx = blockIdx.x * blockDim.x + threadIdx.x;
    if (idx == 0) {
        int off = 0;
        for (int q = 0; q < KSLOTS; q++) {
            g_aoff[q]   = off;
            g_cursor[q] = off;
            off += ((g_hist[q] + TILE - 1) / TILE) * TILE;  // tile-align each bin
        }
        g_aoff[KSLOTS] = off;
        int p = 0;
        for (int b = 0; b < B; b++) { g_segoff[b] = p; p += ss[b]; }
        g_segoff[B] = N;
    }
    for (int e = idx; e < total; e += gridDim.x * blockDim.x) {
        g_si[e] = -1;
        g_sj[e] = 0;
    }
}

__global__ void k_scatter(const int* __restrict__ i, const int* __restrict__ j,
                          const int* __restrict__ k, int E) {
    for (int e = blockIdx.x * blockDim.x + threadIdx.x; e < E;
         e += gridDim.x * blockDim.x) {
        int kk  = k[e];
        int pos = atomicAdd(&g_cursor[kk], 1);
        g_si[pos] = i[e];
        g_sj[pos] = j[e];
    }
}

// ---------------- utility ---------------------------------------------------
__global__ void k_zerobuf(float4* __restrict__ p, int n4) {
    float4 z = make_float4(0.f, 0.f, 0.f, 0.f);
    for (int q = blockIdx.x * blockDim.x + threadIdx.x; q < n4;
         q += gridDim.x * blockDim.x)
        p[q] = z;
}

// ---------------- fused gather-GEMM-scatter conv -----------------------------
// Tile = 128 edges of one kernel slot k, 128 threads.
// Thread (warp w = og, lane l): edges {4l..4l+3}, outputs [og*16, og*16+16).
// X staged TRANSPOSED in smem: Xs[c][e], stride 128 floats.
//   - gather STS: lanes write distinct e at the same c -> conflict-free
//   - compute: one LDS.128 yields 4 edges' x values; W loads are broadcast
// Per c-step: 5 LDS.128 + 32 FFMA2 (f32x2) -> FMA-pipe bound.
__global__ void __launch_bounds__(CTHREADS)
k_conv(const float* __restrict__ xin, const float* __restrict__ Wall,
       float* __restrict__ out) {
    extern __shared__ float smem[];
    float* Ws = smem;              // [64][64]  W[k] row-major (c, o) : 16 KB
    float* Xs = smem + 4096;       // [64][128] transposed x tile      : 32 KB

    int tb = blockIdx.x * TILE;
    if (tb >= g_aoff[KSLOTS]) return;

    int kk = 0;
    while (g_aoff[kk + 1] <= tb) kk++;   // uniform, L1-cached

    // stage W[k] (coalesced float4)
    const float4* Wk4 = reinterpret_cast<const float4*>(Wall + (size_t)kk * CDIM * CDIM);
    #pragma unroll
    for (int t = threadIdx.x; t < (CDIM * CDIM) / 4; t += CTHREADS)
        reinterpret_cast<float4*>(Ws)[t] = __ldg(Wk4 + t);

    // gather: thread t loads edge t's full x row, writes transposed
    {
        int t  = threadIdx.x;
        int jj = g_sj[tb + t];
        const float4* xr = reinterpret_cast<const float4*>(xin + (size_t)jj * CDIM);
        #pragma unroll
        for (int q = 0; q < 16; q++) {
            float4 v = __ldg(xr + q);
            Xs[(4 * q + 0) * TILE + t] = v.x;
            Xs[(4 * q + 1) * TILE + t] = v.y;
            Xs[(4 * q + 2) * TILE + t] = v.z;
            Xs[(4 * q + 3) * TILE + t] = v.w;
        }
    }
    __syncthreads();

    int lane = threadIdx.x & 31;
    int og   = threadIdx.x >> 5;

    unsigned long long acc[32];          // [edge q 0..3][f32x2 pair p 0..7]
    #pragma unroll
    for (int m = 0; m < 32; m++) acc[m] = 0ull;

    const float* xb = Xs + 4 * lane;
    const float* wb = Ws + og * 16;

    #pragma unroll 4
    for (int c = 0; c < CDIM; c++) {
        float4 xv = *reinterpret_cast<const float4*>(xb + c * TILE);
        const ulonglong2* wr = reinterpret_cast<const ulonglong2*>(wb + c * CDIM);
        ulonglong2 w0 = wr[0], w1 = wr[1], w2 = wr[2], w3 = wr[3];
        unsigned long long w[8] = {w0.x, w0.y, w1.x, w1.y, w2.x, w2.y, w3.x, w3.y};
        float xs4[4] = {xv.x, xv.y, xv.z, xv.w};
        #pragma unroll
        for (int q = 0; q < 4; q++) {
            unsigned long long xp;
            asm("mov.b64 %0, {%1,%1};" : "=l"(xp) : "r"(__float_as_uint(xs4[q])));
            #pragma unroll
            for (int p = 0; p < 8; p++)
                asm("fma.rn.f32x2 %0, %1, %2, %0;"
                    : "+l"(acc[q * 8 + p]) : "l"(xp), "l"(w[p]));
        }
    }

    // scatter: 4 edges x 16 outputs as float4 REDs
    #pragma unroll
    for (int q = 0; q < 4; q++) {
        int ii = g_si[tb + 4 * lane + q];
        if (ii < 0) continue;   // pad slot
        float* orow = out + (size_t)ii * CDIM + og * 16;
        #pragma unroll
        for (int p = 0; p < 4; p++) {
            unsigned long long a0 = acc[q * 8 + 2 * p];
            unsigned long long a1 = acc[q * 8 + 2 * p + 1];
            float4 v;
            v.x = __uint_as_float((unsigned)(a0 & 0xffffffffull));
            v.y = __uint_as_float((unsigned)(a0 >> 32));
            v.z = __uint_as_float((unsigned)(a1 & 0xffffffffull));
            v.w = __uint_as_float((unsigned)(a1 >> 32));
            atomicAdd(reinterpret_cast<float4*>(orow) + p, v);
        }
    }
}

// ---------------- ragged LayerNorm ------------------------------------------
__global__ void k_zstats(int B) {
    int s = blockIdx.x * blockDim.x + threadIdx.x;
    if (s < B) { g_s1[s] = 0.0; g_s2[s] = 0.0; }
}

__global__ void k_stats(const float* __restrict__ v) {
    int seg = blockIdx.x;
    long long e0 = (long long)g_segoff[seg] * CDIM;
    long long e1 = (long long)g_segoff[seg + 1] * CDIM;
    double s1 = 0.0, s2 = 0.0;
    long long stride = (long long)gridDim.y * blockDim.x;
    for (long long idx = e0 + (long long)blockIdx.y * blockDim.x + threadIdx.x;
         idx < e1; idx += stride) {
        double d = (double)v[idx];
        s1 += d;
        s2 += d * d;
    }
    #pragma unroll
    for (int o = 16; o; o >>= 1) {
        s1 += __shfl_down_sync(0xffffffffu, s1, o);
        s2 += __shfl_down_sync(0xffffffffu, s2, o);
    }
    __shared__ double w1[8], w2[8];
    int wid = threadIdx.x >> 5, lid = threadIdx.x & 31;
    if (lid == 0) { w1[wid] = s1; w2[wid] = s2; }
    __syncthreads();
    if (threadIdx.x == 0) {
        double a = 0.0, b = 0.0;
        int nw = blockDim.x >> 5;
        for (int q = 0; q < nw; q++) { a += w1[q]; b += w2[q]; }
        atomicAdd(&g_s1[seg], a);
        atomicAdd(&g_s2[seg], b);
    }
}

__global__ void k_finalize(int B) {
    int s = blockIdx.x * blockDim.x + threadIdx.x;
    if (s < B) {
        double cnt  = (double)(g_segoff[s + 1] - g_segoff[s]) * (double)CDIM;
        double mean = g_s1[s] / cnt;
        double var  = g_s2[s] / cnt - mean * mean;
        g_mean[s] = (float)mean;
        g_invs[s] = rsqrtf((float)var + 1e-5f);
    }
}

__device__ __forceinline__ int find_seg(int p, int B) {
    int s = 0;
    #pragma unroll 1
    while (s + 1 < B && __ldg(&g_segoff[s + 1]) <= p) s++;
    return s;
}

// LN + relu; also zeroes the source accumulator buffer for the next conv
__global__ void k_norm_relu(float* __restrict__ v,
                            const float* __restrict__ gamma,
                            const float* __restrict__ beta,
                            float* __restrict__ o, int N, int B) {
    int total = N * (CDIM / 4);
    float4 z = make_float4(0.f, 0.f, 0.f, 0.f);
    for (int q = blockIdx.x * blockDim.x + threadIdx.x; q < total;
         q += gridDim.x * blockDim.x) {
        int p  = q >> 4;
        int c4 = (q & 15) << 2;
        int s  = find_seg(p, B);
        float mu = g_mean[s], inv = g_invs[s];
        float4 x4 = reinterpret_cast<float4*>(v)[q];
        reinterpret_cast<float4*>(v)[q] = z;   // fused zero for conv2
        float4 gg = __ldg(reinterpret_cast<const float4*>(gamma + c4));
        float4 bb = __ldg(reinterpret_cast<const float4*>(beta + c4));
        float4 r;
        r.x = fmaxf(fmaf((x4.x - mu) * inv, gg.x, bb.x), 0.f);
        r.y = fmaxf(fmaf((x4.y - mu) * inv, gg.y, bb.y), 0.f);
        r.z = fmaxf(fmaf((x4.z - mu) * inv, gg.z, bb.z), 0.f);
        r.w = fmaxf(fmaf((x4.w - mu) * inv, gg.w, bb.w), 0.f);
        reinterpret_cast<float4*>(o)[q] = r;
    }
}

__global__ void k_norm_res_relu(const float* __restrict__ v,
                                const float* __restrict__ gamma,
                                const float* __restrict__ beta,
                                const float* __restrict__ xin,
                                float* __restrict__ o, int N, int B) {
    int total = N * (CDIM / 4);
    for (int q = blockIdx.x * blockDim.x + threadIdx.x; q < total;
         q += gridDim.x * blockDim.x) {
        int p  = q >> 4;
        int c4 = (q & 15) << 2;
        int s  = find_seg(p, B);
        float mu = g_mean[s], inv = g_invs[s];
        float4 x4 = reinterpret_cast<const float4*>(v)[q];
        float4 rx = __ldg(reinterpret_cast<const float4*>(xin) + q);
        float4 gg = __ldg(reinterpret_cast<const float4*>(gamma + c4));
        float4 bb = __ldg(reinterpret_cast<const float4*>(beta + c4));
        float4 r;
        r.x = fmaxf(fmaf((x4.x - mu) * inv, gg.x, bb.x) + rx.x, 0.f);
        r.y = fmaxf(fmaf((x4.y - mu) * inv, gg.y, bb.y) + rx.y, 0.f);
        r.z = fmaxf(fmaf((x4.z - mu) * inv, gg.z, bb.z) + rx.z, 0.f);
        r.w = fmaxf(fmaf((x4.w - mu) * inv, gg.w, bb.w) + rx.w, 0.f);
        reinterpret_cast<float4*>(o)[q] = r;
    }
}

// ---------------- host-side launch sequence ---------------------------------
extern "C" void kernel_launch(void* const* d_in, const int* in_sizes, int n_in,
                              void* d_out, int out_size) {
    (void)n_in; (void)out_size;
    const float* x  = (const float*)d_in[0];
    const float* W1 = (const float*)d_in[1];
    const float* g1 = (const float*)d_in[2];
    const float* b1 = (const float*)d_in[3];
    const float* W2 = (const float*)d_in[4];
    const float* g2 = (const float*)d_in[5];
    const float* b2 = (const float*)d_in[6];
    const int*   ei = (const int*)d_in[7];
    const int*   ej = (const int*)d_in[8];
    const int*   ek = (const int*)d_in[9];
    const int*   ss = (const int*)d_in[10];

    int N = in_sizes[0] / CDIM;
    int E = in_sizes[7];
    int B = in_sizes[10];
    float* out = (float*)d_out;

    float *pA, *pB;
    cudaGetSymbolAddress((void**)&pA, g_bufA);
    cudaGetSymbolAddress((void**)&pB, g_bufB);

    const int SMEM = 48 * 1024;   // Ws 16K + Xs 32K
    static int smem_set = 0;
    if (!smem_set) {
        cudaFuncSetAttribute(k_conv, cudaFuncAttributeMaxDynamicSharedMemorySize, SMEM);
        smem_set = 1;
    }

    int n4    = N * (CDIM / 4);
    int nb    = (E + KSLOTS * (TILE - 1) + TILE - 1) / TILE;
    int statB = (B + 255) / 256;
    int fillN = E + EPAD; if (fillN > EMAX) fillN = EMAX;

    // sort + zero (ordered so k_conv is launch #6 -> ncu -s 5 -c 1 profiles it)
    k_zero_meta<<<1, 32>>>();                       // 1
    k_zerobuf<<<512, 256>>>((float4*)pA, n4);       // 2
    k_hist<<<256, 256>>>(ek, E);                    // 3
    k_fill_scan<<<256, 256>>>(fillN, ss, B, N);     // 4
    k_scatter<<<256, 256>>>(ei, ej, ek, E);         // 5

    // conv1 -> LN1 -> relu (LN also re-zeros pA for conv2)
    k_conv<<<nb, CTHREADS, SMEM>>>(x, W1, pA);      // 6  <-- profiled
    k_zstats<<<statB, 256>>>(B);
    k_stats<<<dim3(B, 128), 256>>>(pA);
    k_finalize<<<statB, 256>>>(B);
    k_norm_relu<<<512, 256>>>(pA, g1, b1, pB, N, B);

    // conv2 -> LN2 -> +x -> relu
    k_conv<<<nb, CTHREADS, SMEM>>>(pB, W2, pA);
    k_zstats<<<statB, 256>>>(B);
    k_stats<<<dim3(B, 128), 256>>>(pA);
    k_finalize<<<statB, 256>>>(B);
    k_norm_res_relu<<<512, 256>>>(pA, g2, b2, x, out, N, B);
}

// round 7
// speedup vs baseline: 1.4820x; 1.0930x over previous
#include <cuda_runtime.h>
#include <cuda_bf16.h>
#include <cstdint>

#define CDIM     64
#define KSLOTS   27
#define TILE     128
#define NMAX     65536
#define EPAD     (KSLOTS * TILE)
#define EMAX     (1572864 + EPAD)
#define MAXSEG   1024

// smem layout for k_conv: X tiles padded to 144B rows (ldmatrix conflict-free)
#define SM_XH    0
#define SM_XL    18432
#define SM_WH    36864
#define SM_WL    46080
#define SMEM_TOT 55296
#define DSTRIDE  272           // epilogue D tile row stride (68 floats)

// ---------------- device scratch (static: zero-initialized at load) ----------
__device__ float  g_bufA[(size_t)NMAX * CDIM];   // conv accumulators (fp32)
__device__ uint4  g_xh1[(size_t)NMAX * 8], g_xl1[(size_t)NMAX * 8]; // x split
__device__ uint4  g_xh2[(size_t)NMAX * 8], g_xl2[(size_t)NMAX * 8]; // act split
__device__ uint4  g_w1s[KSLOTS * 1024], g_w2s[KSLOTS * 1024]; // Wt split hi/lo
__device__ int    g_si[EMAX];
__device__ int    g_sj[EMAX];
__device__ int    g_hist[KSLOTS];                // invariant: 0 between calls
__device__ int    g_aoff[KSLOTS + 1];
__device__ int    g_cursor[KSLOTS];
__device__ int    g_segoff[MAXSEG + 1];
__device__ double g_s1[MAXSEG], g_s2[MAXSEG];
__device__ float  g_mean[MAXSEG], g_invs[MAXSEG];

// ---------------- helpers -----------------------------------------------------
__device__ __forceinline__ uint32_t smem_u32(const void* p) {
    uint32_t a;
    asm("{ .reg .u64 t; cvta.to.shared.u64 t, %1; cvt.u32.u64 %0, t; }"
        : "=r"(a) : "l"(p));
    return a;
}

#define LDMX4(r, addr) \
    asm volatile("ldmatrix.sync.aligned.m8n8.x4.shared.b16 {%0,%1,%2,%3}, [%4];" \
        : "=r"((r)[0]), "=r"((r)[1]), "=r"((r)[2]), "=r"((r)[3]) : "r"(addr))

#define MMA16816(d, a, b0, b1) \
    asm volatile("mma.sync.aligned.m16n8k16.row.col.f32.bf16.bf16.f32 " \
        "{%0,%1,%2,%3}, {%4,%5,%6,%7}, {%8,%9}, {%0,%1,%2,%3};" \
        : "+f"((d)[0]), "+f"((d)[1]), "+f"((d)[2]), "+f"((d)[3]) \
        : "r"((a)[0]), "r"((a)[1]), "r"((a)[2]), "r"((a)[3]), "r"(b0), "r"(b1))

// bf16 hi/lo split of a float pair -> packed u32s
__device__ __forceinline__ void split2(float a, float b, unsigned& h, unsigned& l) {
    __nv_bfloat16 ha = __float2bfloat16_rn(a), hb = __float2bfloat16_rn(b);
    float ra = a - __bfloat162float(ha);
    float rb = b - __bfloat162float(hb);
    __nv_bfloat16 la = __float2bfloat16_rn(ra), lb = __float2bfloat16_rn(rb);
    h = (unsigned)__bfloat16_as_ushort(ha) | ((unsigned)__bfloat16_as_ushort(hb) << 16);
    l = (unsigned)__bfloat16_as_ushort(la) | ((unsigned)__bfloat16_as_ushort(lb) << 16);
}

// ---------------- prep: pad fill + hist + x split + W transpose/split --------
__global__ void k_prep(const int* __restrict__ ek, int E, int fillN,
                       const float* __restrict__ x, int N,
                       const float* __restrict__ W1, const float* __restrict__ W2) {
    __shared__ int h[KSLOTS];
    if (threadIdx.x < KSLOTS) h[threadIdx.x] = 0;
    __syncthreads();
    int stride = gridDim.x * blockDim.x;
    int idx0   = blockIdx.x * blockDim.x + threadIdx.x;

    for (int e = idx0; e < fillN; e += stride) { g_si[e] = -1; g_sj[e] = 0; }
    for (int e = idx0; e < E; e += stride) atomicAdd(&h[ek[e]], 1);

    // x rows -> bf16 hi/lo
    for (int p = idx0; p < N; p += stride) {
        const float4* xr = reinterpret_cast<const float4*>(x + (size_t)p * CDIM);
        #pragma unroll
        for (int g = 0; g < 8; g++) {
            float4 a = __ldg(xr + 2 * g), b = __ldg(xr + 2 * g + 1);
            uint4 oh, ol;
            split2(a.x, a.y, oh.x, ol.x);
            split2(a.z, a.w, oh.y, ol.y);
            split2(b.x, b.y, oh.z, ol.z);
            split2(b.z, b.w, oh.w, ol.w);
            g_xh1[(size_t)p * 8 + g] = oh;
            g_xl1[(size_t)p * 8 + g] = ol;
        }
    }

    // W -> transposed Wt[o][c], split hi/lo: per k, 4096 ushort hi then 4096 lo
    int wtot = 2 * KSLOTS * CDIM * CDIM;
    for (int q = idx0; q < wtot; q += stride) {
        int which = (q >= KSLOTS * CDIM * CDIM);
        int rem   = which ? q - KSLOTS * CDIM * CDIM : q;
        int kk = rem >> 12;
        int cc = (rem & 4095) >> 6;
        int oo = rem & 63;
        const float* W = which ? W2 : W1;
        float v = __ldg(W + (size_t)kk * 4096 + cc * 64 + oo);
        __nv_bfloat16 hb = __float2bfloat16_rn(v);
        float r = v - __bfloat162float(hb);
        __nv_bfloat16 lb = __float2bfloat16_rn(r);
        unsigned short* dst = reinterpret_cast<unsigned short*>(which ? g_w2s : g_w1s);
        dst[(size_t)kk * 8192 + oo * 64 + cc]        = __bfloat16_as_ushort(hb);
        dst[(size_t)kk * 8192 + 4096 + oo * 64 + cc] = __bfloat16_as_ushort(lb);
    }

    __syncthreads();
    if (threadIdx.x < KSLOTS) atomicAdd(&g_hist[threadIdx.x], h[threadIdx.x]);
}

__global__ void k_scan(const int* __restrict__ ss, int B, int N) {
    if (threadIdx.x == 0 && blockIdx.x == 0) {
        int off = 0;
        for (int q = 0; q < KSLOTS; q++) {
            g_aoff[q]   = off;
            g_cursor[q] = off;
            off += ((g_hist[q] + TILE - 1) / TILE) * TILE;
        }
        g_aoff[KSLOTS] = off;
        int p = 0;
        for (int b = 0; b < B; b++) { g_segoff[b] = p; p += ss[b]; }
        g_segoff[B] = N;
        for (int b = 0; b < B; b++) { g_s1[b] = 0.0; g_s2[b] = 0.0; }
    }
}

__global__ void k_scatter(const int* __restrict__ i, const int* __restrict__ j,
                          const int* __restrict__ k, int E) {
    for (int e = blockIdx.x * blockDim.x + threadIdx.x; e < E;
         e += gridDim.x * blockDim.x) {
        int kk  = k[e];
        int pos = atomicAdd(&g_cursor[kk], 1);
        g_si[pos] = i[e];
        g_sj[pos] = j[e];
    }
    // reset hist for next replay (not read by this kernel)
    if (blockIdx.x == 0 && threadIdx.x < KSLOTS) g_hist[threadIdx.x] = 0;
}

// ---------------- tensor-core conv (mma.sync bf16 split, 3-term) -------------
// Tile = 128 edges x 64 outputs. 4 warps; warp w owns edges [32w, 32w+32)
// (2 m16 tiles) x all 64 outputs (8 n8 tiles). K = 64 in 4 k16 steps.
__global__ void __launch_bounds__(128)
k_conv(const uint4* __restrict__ gXh, const uint4* __restrict__ gXl,
       const uint4* __restrict__ gW, float* __restrict__ out) {
    extern __shared__ char smem[];
    int tb = blockIdx.x * TILE;
    if (tb >= g_aoff[KSLOTS]) return;
    int kk = 0;
    while (g_aoff[kk + 1] <= tb) kk++;

    int tid = threadIdx.x, w = tid >> 5, lane = tid & 31;

    // stage Wt[k] hi/lo: rows o (64), stride 144B
    const uint4* ws = gW + (size_t)kk * 1024;
    #pragma unroll
    for (int q = 0; q < 4; q++) {
        int idx = tid + 128 * q;
        int o = idx >> 3, c8 = idx & 7;
        *reinterpret_cast<uint4*>(smem + SM_WH + o * 144 + c8 * 16) = __ldg(ws + idx);
        *reinterpret_cast<uint4*>(smem + SM_WL + o * 144 + c8 * 16) = __ldg(ws + 512 + idx);
    }
    // gather edge rows (128B hi + lo), stride 144B
    int jj = g_sj[tb + tid];
    const uint4* xh = gXh + (size_t)jj * 8;
    const uint4* xl = gXl + (size_t)jj * 8;
    #pragma unroll
    for (int q = 0; q < 8; q++) {
        *reinterpret_cast<uint4*>(smem + SM_XH + tid * 144 + q * 16) = __ldg(xh + q);
        *reinterpret_cast<uint4*>(smem + SM_XL + tid * 144 + q * 16) = __ldg(xl + q);
    }
    __syncthreads();

    uint32_t sb = smem_u32(smem);

    float acc[2][8][4];
    #pragma unroll
    for (int a = 0; a < 2; a++)
        #pragma unroll
        for (int b = 0; b < 8; b++)
            #pragma unroll
            for (int c = 0; c < 4; c++) acc[a][b][c] = 0.f;

    // per-lane ldmatrix base addresses
    uint32_t aH[2], aL[2], bH[4], bL[4];
    {
        int arow  = lane & 15;
        int abyte = (lane >> 4) * 16;          // k-half select
        #pragma unroll
        for (int mt = 0; mt < 2; mt++) {
            int row = w * 32 + mt * 16 + arow;
            aH[mt] = sb + SM_XH + row * 144 + abyte;
            aL[mt] = sb + SM_XL + row * 144 + abyte;
        }
        int nsub  = (lane & 7) + 8 * (lane >> 4);   // n within 16-octet pair
        int kbyte = ((lane >> 3) & 1) * 16;         // k-half select
        #pragma unroll
        for (int np = 0; np < 4; np++) {
            int nn = np * 16 + nsub;
            bH[np] = sb + SM_WH + nn * 144 + kbyte;
            bL[np] = sb + SM_WL + nn * 144 + kbyte;
        }
    }

    #pragma unroll
    for (int ks = 0; ks < 4; ks++) {
        uint32_t ah[2][4], al[2][4];
        #pragma unroll
        for (int mt = 0; mt < 2; mt++) {
            LDMX4(ah[mt], aH[mt] + ks * 32);
            LDMX4(al[mt], aL[mt] + ks * 32);
        }
        #pragma unroll
        for (int np = 0; np < 4; np++) {
            uint32_t bh[4], bl[4];
            LDMX4(bh, bH[np] + ks * 32);
            LDMX4(bl, bL[np] + ks * 32);
            #pragma unroll
            for (int mt = 0; mt < 2; mt++) {
                float* d0 = acc[mt][2 * np];
                float* d1 = acc[mt][2 * np + 1];
                MMA16816(d0, ah[mt], bh[0], bh[1]);
                MMA16816(d0, al[mt], bh[0], bh[1]);
                MMA16816(d0, ah[mt], bl[0], bl[1]);
                MMA16816(d1, ah[mt], bh[2], bh[3]);
                MMA16816(d1, al[mt], bh[2], bh[3]);
                MMA16816(d1, ah[mt], bl[2], bl[3]);
            }
        }
    }
    __syncthreads();   // done reading X/W smem; reuse for D transpose

    // store D frags to smem [128][68 floats]
    {
        int r0 = w * 32 + (lane >> 2);
        int cb = 2 * (lane & 3);
        #pragma unroll
        for (int mt = 0; mt < 2; mt++) {
            #pragma unroll
            for (int nt = 0; nt < 8; nt++) {
                int col = nt * 8 + cb;
                float* base = reinterpret_cast<float*>(smem + (r0 + mt * 16) * DSTRIDE + col * 4);
                *reinterpret_cast<float2*>(base) =
                    make_float2(acc[mt][nt][0], acc[mt][nt][1]);
                float* base2 = reinterpret_cast<float*>(smem + (r0 + mt * 16 + 8) * DSTRIDE + col * 4);
                *reinterpret_cast<float2*>(base2) =
                    make_float2(acc[mt][nt][2], acc[mt][nt][3]);
            }
        }
    }
    __syncthreads();

    // scatter: edge row -> 16 float4 REDs
    int ii = g_si[tb + tid];
    if (ii >= 0) {
        float* orow = out + (size_t)ii * CDIM;
        #pragma unroll
        for (int q = 0; q < 16; q++) {
            float4 v = *reinterpret_cast<float4*>(smem + tid * DSTRIDE + q * 16);
            atomicAdd(reinterpret_cast<float4*>(orow) + q, v);
        }
    }
}

// ---------------- ragged LayerNorm ------------------------------------------
__global__ void k_stats(const float* __restrict__ v) {
    int seg = blockIdx.x;
    long long e0 = (long long)g_segoff[seg] * CDIM;
    long long e1 = (long long)g_segoff[seg + 1] * CDIM;
    double s1 = 0.0, s2 = 0.0;
    long long stride = (long long)gridDim.y * blockDim.x;
    for (long long idx = e0 + (long long)blockIdx.y * blockDim.x + threadIdx.x;
         idx < e1; idx += stride) {
        double d = (double)v[idx];
        s1 += d;
        s2 += d * d;
    }
    #pragma unroll
    for (int o = 16; o; o >>= 1) {
        s1 += __shfl_down_sync(0xffffffffu, s1, o);
        s2 += __shfl_down_sync(0xffffffffu, s2, o);
    }
    __shared__ double w1[8], w2[8];
    int wid = threadIdx.x >> 5, lid = threadIdx.x & 31;
    if (lid == 0) { w1[wid] = s1; w2[wid] = s2; }
    __syncthreads();
    if (threadIdx.x == 0) {
        double a = 0.0, b = 0.0;
        int nw = blockDim.x >> 5;
        for (int q = 0; q < nw; q++) { a += w1[q]; b += w2[q]; }
        atomicAdd(&g_s1[seg], a);
        atomicAdd(&g_s2[seg], b);
    }
}

__global__ void k_finalize(int B) {
    int s = blockIdx.x * blockDim.x + threadIdx.x;
    if (s < B) {
        double cnt  = (double)(g_segoff[s + 1] - g_segoff[s]) * (double)CDIM;
        double mean = g_s1[s] / cnt;
        double var  = g_s2[s] / cnt - mean * mean;
        g_mean[s] = (float)mean;
        g_invs[s] = rsqrtf((float)var + 1e-5f);
    }
}

__device__ __forceinline__ int find_seg(int p, int B) {
    int s = 0;
    #pragma unroll 1
    while (s + 1 < B && __ldg(&g_segoff[s + 1]) <= p) s++;
    return s;
}

// LN1 + relu -> bf16 hi/lo split; re-zeroes accumulator + layer-2 stats
__global__ void k_norm_relu(float* __restrict__ v,
                            const float* __restrict__ gamma,
                            const float* __restrict__ beta,
                            uint4* __restrict__ oh, uint4* __restrict__ ol,
                            int N, int B) {
    if (blockIdx.x == 0 && threadIdx.x < B) {
        g_s1[threadIdx.x] = 0.0;
        g_s2[threadIdx.x] = 0.0;
    }
    int total = N * (CDIM / 4);
    float4 z = make_float4(0.f, 0.f, 0.f, 0.f);
    for (int q = blockIdx.x * blockDim.x + threadIdx.x; q < total;
         q += gridDim.x * blockDim.x) {
        int p  = q >> 4;
        int c4 = (q & 15) << 2;
        int s  = find_seg(p, B);
        float mu = g_mean[s], inv = g_invs[s];
        float4 x4 = reinterpret_cast<float4*>(v)[q];
        reinterpret_cast<float4*>(v)[q] = z;   // re-zero for conv2
        float4 gg = __ldg(reinterpret_cast<const float4*>(gamma + c4));
        float4 bb = __ldg(reinterpret_cast<const float4*>(beta + c4));
        float r0 = fmaxf(fmaf((x4.x - mu) * inv, gg.x, bb.x), 0.f);
        float r1 = fmaxf(fmaf((x4.y - mu) * inv, gg.y, bb.y), 0.f);
        float r2 = fmaxf(fmaf((x4.z - mu) * inv, gg.z, bb.z), 0.f);
        float r3 = fmaxf(fmaf((x4.w - mu) * inv, gg.w, bb.w), 0.f);
        uint2 hh, ll;
        split2(r0, r1, hh.x, ll.x);
        split2(r2, r3, hh.y, ll.y);
        reinterpret_cast<uint2*>(oh)[(size_t)p * 16 + (q & 15)] = hh;
        reinterpret_cast<uint2*>(ol)[(size_t)p * 16 + (q & 15)] = ll;
    }
}

// LN2 + residual + relu; re-zeroes accumulator for the next replay
__global__ void k_norm_res_relu(float* __restrict__ v,
                                const float* __restrict__ gamma,
                                const float* __restrict__ beta,
                                const float* __restrict__ xin,
                                float* __restrict__ o, int N, int B) {
    int total = N * (CDIM / 4);
    float4 z = make_float4(0.f, 0.f, 0.f, 0.f);
    for (int q = blockIdx.x * blockDim.x + threadIdx.x; q < total;
         q += gridDim.x * blockDim.x) {
        int p  = q >> 4;
        int c4 = (q & 15) << 2;
        int s  = find_seg(p, B);
        float mu = g_mean[s], inv = g_invs[s];
        float4 x4 = reinterpret_cast<float4*>(v)[q];
        reinterpret_cast<float4*>(v)[q] = z;   // re-zero for next call
        float4 rx = __ldg(reinterpret_cast<const float4*>(xin) + q);
        float4 gg = __ldg(reinterpret_cast<const float4*>(gamma + c4));
        float4 bb = __ldg(reinterpret_cast<const float4*>(beta + c4));
        float4 r;
        r.x = fmaxf(fmaf((x4.x - mu) * inv, gg.x, bb.x) + rx.x, 0.f);
        r.y = fmaxf(fmaf((x4.y - mu) * inv, gg.y, bb.y) + rx.y, 0.f);
        r.z = fmaxf(fmaf((x4.z - mu) * inv, gg.z, bb.z) + rx.z, 0.f);
        r.w = fmaxf(fmaf((x4.w - mu) * inv, gg.w, bb.w) + rx.w, 0.f);
        reinterpret_cast<float4*>(o)[q] = r;
    }
}

// ---------------- host-side launch sequence ---------------------------------
extern "C" void kernel_launch(void* const* d_in, const int* in_sizes, int n_in,
                              void* d_out, int out_size) {
    (void)n_in; (void)out_size;
    const float* x  = (const float*)d_in[0];
    const float* W1 = (const float*)d_in[1];
    const float* g1 = (const float*)d_in[2];
    const float* b1 = (const float*)d_in[3];
    const float* W2 = (const float*)d_in[4];
    const float* g2 = (const float*)d_in[5];
    const float* b2 = (const float*)d_in[6];
    const int*   ei = (const int*)d_in[7];
    const int*   ej = (const int*)d_in[8];
    const int*   ek = (const int*)d_in[9];
    const int*   ss = (const int*)d_in[10];

    int N = in_sizes[0] / CDIM;
    int E = in_sizes[7];
    int B = in_sizes[10];
    float* out = (float*)d_out;

    float* pA; cudaGetSymbolAddress((void**)&pA, g_bufA);
    uint4 *xh1, *xl1, *xh2, *xl2, *w1s, *w2s;
    cudaGetSymbolAddress((void**)&xh1, g_xh1);
    cudaGetSymbolAddress((void**)&xl1, g_xl1);
    cudaGetSymbolAddress((void**)&xh2, g_xh2);
    cudaGetSymbolAddress((void**)&xl2, g_xl2);
    cudaGetSymbolAddress((void**)&w1s, g_w1s);
    cudaGetSymbolAddress((void**)&w2s, g_w2s);

    cudaFuncSetAttribute(k_conv, cudaFuncAttributeMaxDynamicSharedMemorySize, SMEM_TOT);

    int fillN = E + EPAD; if (fillN > EMAX) fillN = EMAX;
    int statB = (B + 31) / 32;
    int nb    = (E + KSLOTS * (TILE - 1) + TILE - 1) / TILE;

    // replay-state invariants: g_hist=0 (end of k_scatter), g_bufA=0 (LN epilogues)
    k_prep<<<1024, 256>>>(ek, E, fillN, x, N, W1, W2);            // L1
    k_scan<<<1, 1>>>(ss, B, N);                                    // L2
    k_scatter<<<256, 256>>>(ei, ej, ek, E);                        // L3

    k_conv<<<nb, 128, SMEM_TOT>>>(xh1, xl1, w1s, pA);              // L4 (profiled)
    k_stats<<<dim3(B, 128), 256>>>(pA);                            // L5
    k_finalize<<<statB, 32>>>(B);                                  // L6
    k_norm_relu<<<512, 256>>>(pA, g1, b1, xh2, xl2, N, B);         // L7

    k_conv<<<nb, 128, SMEM_TOT>>>(xh2, xl2, w2s, pA);              // L8
    k_stats<<<dim3(B, 128), 256>>>(pA);                            // L9
    k_finalize<<<statB, 32>>>(B);                                  // L10
    k_norm_res_relu<<<512, 256>>>(pA, g2, b2, x, out, N, B);       // L11
}

// round 8
// speedup vs baseline: 2.7500x; 1.8555x over previous
#include <cuda_runtime.h>
#include <cuda_bf16.h>
#include <cstdint>

#define CDIM     64
#define KSLOTS   27
#define TILE     128
#define NMAX     65536
#define EPAD     (KSLOTS * TILE)
#define EMAX     (1572864 + EPAD)
#define MAXSEG   1024

// smem layout for k_conv: rows padded to 144B (ldmatrix conflict-free)
#define SM_XH    0
#define SM_XL    18432
#define SM_WH    36864
#define SM_WL    46080
#define SMEM_TOT 55296

// ---------------- device scratch (static: zero-initialized at load) ----------
__device__ float  g_bufA[(size_t)NMAX * CDIM];   // conv accumulators (fp32)
__device__ uint4  g_xh1[(size_t)NMAX * 8], g_xl1[(size_t)NMAX * 8]; // x split
__device__ uint4  g_xh2[(size_t)NMAX * 8], g_xl2[(size_t)NMAX * 8]; // act split
__device__ uint4  g_w1s[KSLOTS * 1024], g_w2s[KSLOTS * 1024]; // Wt split hi/lo
__device__ int2   g_sij[EMAX];                   // sorted (target, source); pad=(-1,0)
__device__ int    g_hist[KSLOTS];                // invariant: 0 between calls
__device__ int    g_aoff[KSLOTS + 1];
__device__ int    g_cursor[KSLOTS];
__device__ int    g_segoff[MAXSEG + 1];
__device__ double g_s1[MAXSEG], g_s2[MAXSEG];
__device__ float  g_mean[MAXSEG], g_invs[MAXSEG];

// ---------------- helpers -----------------------------------------------------
__device__ __forceinline__ uint32_t smem_u32(const void* p) {
    uint32_t a;
    asm("{ .reg .u64 t; cvta.to.shared.u64 t, %1; cvt.u32.u64 %0, t; }"
        : "=r"(a) : "l"(p));
    return a;
}
__device__ __forceinline__ void cpa16(uint32_t d, const void* s) {
    asm volatile("cp.async.cg.shared.global [%0], [%1], 16;"
                 :: "r"(d), "l"(s) : "memory");
}
#define CPA_COMMIT() asm volatile("cp.async.commit_group;" ::: "memory")
#define CPA_WAIT0()  asm volatile("cp.async.wait_group 0;" ::: "memory")

#define LDMX4(r, addr) \
    asm volatile("ldmatrix.sync.aligned.m8n8.x4.shared.b16 {%0,%1,%2,%3}, [%4];" \
        : "=r"((r)[0]), "=r"((r)[1]), "=r"((r)[2]), "=r"((r)[3]) : "r"(addr))

#define MMA16816(d, a, b0, b1) \
    asm volatile("mma.sync.aligned.m16n8k16.row.col.f32.bf16.bf16.f32 " \
        "{%0,%1,%2,%3}, {%4,%5,%6,%7}, {%8,%9}, {%0,%1,%2,%3};" \
        : "+f"((d)[0]), "+f"((d)[1]), "+f"((d)[2]), "+f"((d)[3]) \
        : "r"((a)[0]), "r"((a)[1]), "r"((a)[2]), "r"((a)[3]), "r"(b0), "r"(b1))

// bf16 hi/lo split of a float pair -> packed u32s
__device__ __forceinline__ void split2(float a, float b, unsigned& h, unsigned& l) {
    __nv_bfloat16 ha = __float2bfloat16_rn(a), hb = __float2bfloat16_rn(b);
    float ra = a - __bfloat162float(ha);
    float rb = b - __bfloat162float(hb);
    __nv_bfloat16 la = __float2bfloat16_rn(ra), lb = __float2bfloat16_rn(rb);
    h = (unsigned)__bfloat16_as_ushort(ha) | ((unsigned)__bfloat16_as_ushort(hb) << 16);
    l = (unsigned)__bfloat16_as_ushort(la) | ((unsigned)__bfloat16_as_ushort(lb) << 16);
}

// ---------------- prep: pad fill + hist + x split + W transpose/split --------
__global__ void k_prep(const int* __restrict__ ek, int E, int fillN,
                       const float* __restrict__ x, int N,
                       const float* __restrict__ W1, const float* __restrict__ W2) {
    __shared__ int h[KSLOTS];
    if (threadIdx.x < KSLOTS) h[threadIdx.x] = 0;
    __syncthreads();
    int stride = gridDim.x * blockDim.x;
    int idx0   = blockIdx.x * blockDim.x + threadIdx.x;

    for (int e = idx0; e < fillN; e += stride) g_sij[e] = make_int2(-1, 0);
    for (int e = idx0; e < E; e += stride) atomicAdd(&h[ek[e]], 1);

    // x rows -> bf16 hi/lo
    for (int p = idx0; p < N; p += stride) {
        const float4* xr = reinterpret_cast<const float4*>(x + (size_t)p * CDIM);
        #pragma unroll
        for (int g = 0; g < 8; g++) {
            float4 a = __ldg(xr + 2 * g), b = __ldg(xr + 2 * g + 1);
            uint4 oh, ol;
            split2(a.x, a.y, oh.x, ol.x);
            split2(a.z, a.w, oh.y, ol.y);
            split2(b.x, b.y, oh.z, ol.z);
            split2(b.z, b.w, oh.w, ol.w);
            g_xh1[(size_t)p * 8 + g] = oh;
            g_xl1[(size_t)p * 8 + g] = ol;
        }
    }

    // W -> transposed Wt[o][c], split hi/lo: per k, 4096 ushort hi then 4096 lo
    int wtot = 2 * KSLOTS * CDIM * CDIM;
    for (int q = idx0; q < wtot; q += stride) {
        int which = (q >= KSLOTS * CDIM * CDIM);
        int rem   = which ? q - KSLOTS * CDIM * CDIM : q;
        int kk = rem >> 12;
        int cc = (rem & 4095) >> 6;
        int oo = rem & 63;
        const float* W = which ? W2 : W1;
        float v = __ldg(W + (size_t)kk * 4096 + cc * 64 + oo);
        __nv_bfloat16 hb = __float2bfloat16_rn(v);
        float r = v - __bfloat162float(hb);
        __nv_bfloat16 lb = __float2bfloat16_rn(r);
        unsigned short* dst = reinterpret_cast<unsigned short*>(which ? g_w2s : g_w1s);
        dst[(size_t)kk * 8192 + oo * 64 + cc]        = __bfloat16_as_ushort(hb);
        dst[(size_t)kk * 8192 + 4096 + oo * 64 + cc] = __bfloat16_as_ushort(lb);
    }

    __syncthreads();
    if (threadIdx.x < KSLOTS) atomicAdd(&g_hist[threadIdx.x], h[threadIdx.x]);
}

__global__ void k_scan(const int* __restrict__ ss, int B, int N) {
    if (threadIdx.x == 0 && blockIdx.x == 0) {
        int off = 0;
        for (int q = 0; q < KSLOTS; q++) {
            g_aoff[q]   = off;
            g_cursor[q] = off;
            off += ((g_hist[q] + TILE - 1) / TILE) * TILE;
        }
        g_aoff[KSLOTS] = off;
        int p = 0;
        for (int b = 0; b < B; b++) { g_segoff[b] = p; p += ss[b]; }
        g_segoff[B] = N;
        for (int b = 0; b < B; b++) { g_s1[b] = 0.0; g_s2[b] = 0.0; }
    }
}

// block-aggregated counting-sort scatter: 1 global atomic per (block, slot)
__global__ void k_scatter(const int* __restrict__ i, const int* __restrict__ j,
                          const int* __restrict__ k, int E) {
    __shared__ int sh[KSLOTS], sbase[KSLOTS];
    int tid = threadIdx.x;
    if (tid < KSLOTS) sh[tid] = 0;
    __syncthreads();
    int e = blockIdx.x * blockDim.x + tid;
    int kk = 0, rank = 0;
    bool valid = (e < E);
    if (valid) {
        kk   = k[e];
        rank = atomicAdd(&sh[kk], 1);
    }
    __syncthreads();
    if (tid < KSLOTS && sh[tid] > 0)
        sbase[tid] = atomicAdd(&g_cursor[tid], sh[tid]);
    __syncthreads();
    if (valid) {
        int pos = sbase[kk] + rank;
        g_sij[pos] = make_int2(i[e], j[e]);
    }
    if (blockIdx.x == 0 && tid < KSLOTS) g_hist[tid] = 0;   // reset for replay
}

// ---------------- tensor-core conv (mma.sync bf16 split, 3-term) -------------
// Tile = 128 edges x 64 outputs. Warp w: edges [32w,32w+32) x all 64 outputs.
// cp.async staging; scatter directly from fragments (no D smem round-trip).
__global__ void __launch_bounds__(128)
k_conv(const uint4* __restrict__ gXh, const uint4* __restrict__ gXl,
       const uint4* __restrict__ gW, float* __restrict__ out) {
    extern __shared__ char smem[];
    int tb = blockIdx.x * TILE;
    if (tb >= g_aoff[KSLOTS]) return;
    int kk = 0;
    while (g_aoff[kk + 1] <= tb) kk++;

    int tid = threadIdx.x, w = tid >> 5, lane = tid & 31;
    uint32_t sb = smem_u32(smem);

    // stage Wt[k] hi/lo (rows o, stride 144B) via cp.async
    const uint4* ws = gW + (size_t)kk * 1024;
    #pragma unroll
    for (int q = 0; q < 4; q++) {
        int idx = tid + 128 * q;
        int o = idx >> 3, c8 = idx & 7;
        cpa16(sb + SM_WH + o * 144 + c8 * 16, ws + idx);
        cpa16(sb + SM_WL + o * 144 + c8 * 16, ws + 512 + idx);
    }
    // gather edge rows (128B hi + lo, stride 144B) via cp.async
    int2 ij = g_sij[tb + tid];
    const uint4* xh = gXh + (size_t)ij.y * 8;
    const uint4* xl = gXl + (size_t)ij.y * 8;
    #pragma unroll
    for (int q = 0; q < 8; q++) {
        cpa16(sb + SM_XH + tid * 144 + q * 16, xh + q);
        cpa16(sb + SM_XL + tid * 144 + q * 16, xl + q);
    }
    CPA_COMMIT();
    CPA_WAIT0();
    __syncthreads();

    float acc[2][8][4];
    #pragma unroll
    for (int a = 0; a < 2; a++)
        #pragma unroll
        for (int b = 0; b < 8; b++)
            #pragma unroll
            for (int c = 0; c < 4; c++) acc[a][b][c] = 0.f;

    // per-lane ldmatrix base addresses
    uint32_t aH[2], aL[2], bH[4], bL[4];
    {
        int arow  = lane & 15;
        int abyte = (lane >> 4) * 16;          // k-half select
        #pragma unroll
        for (int mt = 0; mt < 2; mt++) {
            int row = w * 32 + mt * 16 + arow;
            aH[mt] = sb + SM_XH + row * 144 + abyte;
            aL[mt] = sb + SM_XL + row * 144 + abyte;
        }
        int nsub  = (lane & 7) + 8 * (lane >> 4);   // n within 16-octet pair
        int kbyte = ((lane >> 3) & 1) * 16;         // k-half select
        #pragma unroll
        for (int np = 0; np < 4; np++) {
            int nn = np * 16 + nsub;
            bH[np] = sb + SM_WH + nn * 144 + kbyte;
            bL[np] = sb + SM_WL + nn * 144 + kbyte;
        }
    }

    #pragma unroll
    for (int ks = 0; ks < 4; ks++) {
        uint32_t ah[2][4], al[2][4];
        #pragma unroll
        for (int mt = 0; mt < 2; mt++) {
            LDMX4(ah[mt], aH[mt] + ks * 32);
            LDMX4(al[mt], aL[mt] + ks * 32);
        }
        #pragma unroll
        for (int np = 0; np < 4; np++) {
            uint32_t bh[4], bl[4];
            LDMX4(bh, bH[np] + ks * 32);
            LDMX4(bl, bL[np] + ks * 32);
            #pragma unroll
            for (int mt = 0; mt < 2; mt++) {
                float* d0 = acc[mt][2 * np];
                float* d1 = acc[mt][2 * np + 1];
                MMA16816(d0, ah[mt], bh[0], bh[1]);
                MMA16816(d0, al[mt], bh[0], bh[1]);
                MMA16816(d0, ah[mt], bl[0], bl[1]);
                MMA16816(d1, ah[mt], bh[2], bh[3]);
                MMA16816(d1, al[mt], bh[2], bh[3]);
                MMA16816(d1, ah[mt], bl[2], bl[3]);
            }
        }
    }

    // direct fragment scatter: thread owns rows r0, r0+8, r0+16, r0+24
    int r0 = w * 32 + (lane >> 2);
    int i0 = g_sij[tb + r0].x;
    int i1 = g_sij[tb + r0 + 8].x;
    int i2 = g_sij[tb + r0 + 16].x;
    int i3 = g_sij[tb + r0 + 24].x;
    int cb = 2 * (lane & 3);
    float* o0 = out + (size_t)(i0 < 0 ? 0 : i0) * CDIM;
    float* o1 = out + (size_t)(i1 < 0 ? 0 : i1) * CDIM;
    float* o2 = out + (size_t)(i2 < 0 ? 0 : i2) * CDIM;
    float* o3 = out + (size_t)(i3 < 0 ? 0 : i3) * CDIM;
    #pragma unroll
    for (int nt = 0; nt < 8; nt++) {
        int col = nt * 8 + cb;
        if (i0 >= 0) atomicAdd(reinterpret_cast<float2*>(o0 + col),
                               make_float2(acc[0][nt][0], acc[0][nt][1]));
        if (i1 >= 0) atomicAdd(reinterpret_cast<float2*>(o1 + col),
                               make_float2(acc[0][nt][2], acc[0][nt][3]));
        if (i2 >= 0) atomicAdd(reinterpret_cast<float2*>(o2 + col),
                               make_float2(acc[1][nt][0], acc[1][nt][1]));
        if (i3 >= 0) atomicAdd(reinterpret_cast<float2*>(o3 + col),
                               make_float2(acc[1][nt][2], acc[1][nt][3]));
    }
}

// ---------------- ragged LayerNorm ------------------------------------------
__global__ void k_stats(const float* __restrict__ v) {
    int seg = blockIdx.x;
    long long e0 = (long long)g_segoff[seg] * CDIM;
    long long e1 = (long long)g_segoff[seg + 1] * CDIM;
    double s1 = 0.0, s2 = 0.0;
    long long stride = (long long)gridDim.y * blockDim.x;
    for (long long idx = e0 + (long long)blockIdx.y * blockDim.x + threadIdx.x;
         idx < e1; idx += stride) {
        double d = (double)v[idx];
        s1 += d;
        s2 += d * d;
    }
    #pragma unroll
    for (int o = 16; o; o >>= 1) {
        s1 += __shfl_down_sync(0xffffffffu, s1, o);
        s2 += __shfl_down_sync(0xffffffffu, s2, o);
    }
    __shared__ double w1[8], w2[8];
    int wid = threadIdx.x >> 5, lid = threadIdx.x & 31;
    if (lid == 0) { w1[wid] = s1; w2[wid] = s2; }
    __syncthreads();
    if (threadIdx.x == 0) {
        double a = 0.0, b = 0.0;
        int nw = blockDim.x >> 5;
        for (int q = 0; q < nw; q++) { a += w1[q]; b += w2[q]; }
        atomicAdd(&g_s1[seg], a);
        atomicAdd(&g_s2[seg], b);
    }
}

__global__ void k_finalize(int B) {
    int s = blockIdx.x * blockDim.x + threadIdx.x;
    if (s < B) {
        double cnt  = (double)(g_segoff[s + 1] - g_segoff[s]) * (double)CDIM;
        double mean = g_s1[s] / cnt;
        double var  = g_s2[s] / cnt - mean * mean;
        g_mean[s] = (float)mean;
        g_invs[s] = rsqrtf((float)var + 1e-5f);
    }
}

__device__ __forceinline__ int find_seg(int p, int B) {
    int s = 0;
    #pragma unroll 1
    while (s + 1 < B && __ldg(&g_segoff[s + 1]) <= p) s++;
    return s;
}

// LN1 + relu -> bf16 hi/lo split; re-zeroes accumulator + layer-2 stats
__global__ void k_norm_relu(float* __restrict__ v,
                            const float* __restrict__ gamma,
                            const float* __restrict__ beta,
                            uint4* __restrict__ oh, uint4* __restrict__ ol,
                            int N, int B) {
    if (blockIdx.x == 0 && threadIdx.x < B) {
        g_s1[threadIdx.x] = 0.0;
        g_s2[threadIdx.x] = 0.0;
    }
    int total = N * (CDIM / 4);
    float4 z = make_float4(0.f, 0.f, 0.f, 0.f);
    for (int q = blockIdx.x * blockDim.x + threadIdx.x; q < total;
         q += gridDim.x * blockDim.x) {
        int p  = q >> 4;
        int c4 = (q & 15) << 2;
        int s  = find_seg(p, B);
        float mu = g_mean[s], inv = g_invs[s];
        float4 x4 = reinterpret_cast<float4*>(v)[q];
        reinterpret_cast<float4*>(v)[q] = z;   // re-zero for conv2
        float4 gg = __ldg(reinterpret_cast<const float4*>(gamma + c4));
        float4 bb = __ldg(reinterpret_cast<const float4*>(beta + c4));
        float r0 = fmaxf(fmaf((x4.x - mu) * inv, gg.x, bb.x), 0.f);
        float r1 = fmaxf(fmaf((x4.y - mu) * inv, gg.y, bb.y), 0.f);
        float r2 = fmaxf(fmaf((x4.z - mu) * inv, gg.z, bb.z), 0.f);
        float r3 = fmaxf(fmaf((x4.w - mu) * inv, gg.w, bb.w), 0.f);
        uint2 hh, ll;
        split2(r0, r1, hh.x, ll.x);
        split2(r2, r3, hh.y, ll.y);
        reinterpret_cast<uint2*>(oh)[(size_t)p * 16 + (q & 15)] = hh;
        reinterpret_cast<uint2*>(ol)[(size_t)p * 16 + (q & 15)] = ll;
    }
}

// LN2 + residual + relu; re-zeroes accumulator for the next replay
__global__ void k_norm_res_relu(float* __restrict__ v,
                                const float* __restrict__ gamma,
                                const float* __restrict__ beta,
                                const float* __restrict__ xin,
                                float* __restrict__ o, int N, int B) {
    int total = N * (CDIM / 4);
    float4 z = make_float4(0.f, 0.f, 0.f, 0.f);
    for (int q = blockIdx.x * blockDim.x + threadIdx.x; q < total;
         q += gridDim.x * blockDim.x) {
        int p  = q >> 4;
        int c4 = (q & 15) << 2;
        int s  = find_seg(p, B);
        float mu = g_mean[s], inv = g_invs[s];
        float4 x4 = reinterpret_cast<float4*>(v)[q];
        reinterpret_cast<float4*>(v)[q] = z;   // re-zero for next call
        float4 rx = __ldg(reinterpret_cast<const float4*>(xin) + q);
        float4 gg = __ldg(reinterpret_cast<const float4*>(gamma + c4));
        float4 bb = __ldg(reinterpret_cast<const float4*>(beta + c4));
        float4 r;
        r.x = fmaxf(fmaf((x4.x - mu) * inv, gg.x, bb.x) + rx.x, 0.f);
        r.y = fmaxf(fmaf((x4.y - mu) * inv, gg.y, bb.y) + rx.y, 0.f);
        r.z = fmaxf(fmaf((x4.z - mu) * inv, gg.z, bb.z) + rx.z, 0.f);
        r.w = fmaxf(fmaf((x4.w - mu) * inv, gg.w, bb.w) + rx.w, 0.f);
        reinterpret_cast<float4*>(o)[q] = r;
    }
}

// ---------------- host-side launch sequence ---------------------------------
extern "C" void kernel_launch(void* const* d_in, const int* in_sizes, int n_in,
                              void* d_out, int out_size) {
    (void)n_in; (void)out_size;
    const float* x  = (const float*)d_in[0];
    const float* W1 = (const float*)d_in[1];
    const float* g1 = (const float*)d_in[2];
    const float* b1 = (const float*)d_in[3];
    const float* W2 = (const float*)d_in[4];
    const float* g2 = (const float*)d_in[5];
    const float* b2 = (const float*)d_in[6];
    const int*   ei = (const int*)d_in[7];
    const int*   ej = (const int*)d_in[8];
    const int*   ek = (const int*)d_in[9];
    const int*   ss = (const int*)d_in[10];

    int N = in_sizes[0] / CDIM;
    int E = in_sizes[7];
    int B = in_sizes[10];
    float* out = (float*)d_out;

    float* pA; cudaGetSymbolAddress((void**)&pA, g_bufA);
    uint4 *xh1, *xl1, *xh2, *xl2, *w1s, *w2s;
    cudaGetSymbolAddress((void**)&xh1, g_xh1);
    cudaGetSymbolAddress((void**)&xl1, g_xl1);
    cudaGetSymbolAddress((void**)&xh2, g_xh2);
    cudaGetSymbolAddress((void**)&xl2, g_xl2);
    cudaGetSymbolAddress((void**)&w1s, g_w1s);
    cudaGetSymbolAddress((void**)&w2s, g_w2s);

    cudaFuncSetAttribute(k_conv, cudaFuncAttributeMaxDynamicSharedMemorySize, SMEM_TOT);

    int fillN = E + EPAD; if (fillN > EMAX) fillN = EMAX;
    int statB = (B + 31) / 32;
    int nb    = (E + KSLOTS * (TILE - 1) + TILE - 1) / TILE;
    int sgrid = (E + 255) / 256;

    // replay-state invariants: g_hist=0 (end of k_scatter), g_bufA=0 (LN epilogues)
    k_prep<<<1024, 256>>>(ek, E, fillN, x, N, W1, W2);            // L1
    k_scan<<<1, 1>>>(ss, B, N);                                    // L2
    k_scatter<<<sgrid, 256>>>(ei, ej, ek, E);                      // L3

    k_conv<<<nb, 128, SMEM_TOT>>>(xh1, xl1, w1s, pA);              // L4 (profiled)
    k_stats<<<dim3(B, 128), 256>>>(pA);                            // L5
    k_finalize<<<statB, 32>>>(B);                                  // L6
    k_norm_relu<<<512, 256>>>(pA, g1, b1, xh2, xl2, N, B);         // L7

    k_conv<<<nb, 128, SMEM_TOT>>>(xh2, xl2, w2s, pA);              // L8
    k_stats<<<dim3(B, 128), 256>>>(pA);                            // L9
    k_finalize<<<statB, 32>>>(B);                                  // L10
    k_norm_res_relu<<<512, 256>>>(pA, g2, b2, x, out, N, B);       // L11
}